// round 2
// baseline (speedup 1.0000x reference)
#include <cuda_runtime.h>
#include <cuda_fp16.h>
#include <cstdint>

#define VOCAB 50257
#define EMBED 512
#define HID   1024
#define G4    4096
#define NCLS  10
#define B_    64
#define S_    512
#define BS_   (B_*S_)
#define NCTA  128

// ---------------- device scratch (no allocations allowed) ----------------
__device__ __half  g_E16[(size_t)BS_*EMBED];    // gathered embeddings, row r = t*64+b
__device__ __half  g_Wx16[(size_t)G4*EMBED];    // Wg[:, :512] fp16
__device__ __half  g_Wh16[(size_t)G4*HID];      // Wg[:, 512:] fp16, scan-permuted rows
__device__ __half  g_Wa16[(size_t)HID*HID];
__device__ __half  g_Xc [(size_t)BS_*G4];       // x-part of gates (+bg), scan-permuted cols
__device__ __half  g_hs [(size_t)BS_*HID];      // all hidden states, row r = t*64+b
__device__ float   g_energy[BS_];
__device__ float   g_ctx[B_*HID];
__device__ unsigned g_bar;

// ---------------- helpers ----------------
__device__ __forceinline__ void ldmx4(unsigned r[4], const void* p) {
    unsigned a = (unsigned)__cvta_generic_to_shared(p);
    asm volatile("ldmatrix.sync.aligned.m8n8.x4.shared.b16 {%0,%1,%2,%3}, [%4];"
        : "=r"(r[0]), "=r"(r[1]), "=r"(r[2]), "=r"(r[3]) : "r"(a));
}
__device__ __forceinline__ void mma16816(float* c, const unsigned* a, const unsigned* b) {
    asm volatile("mma.sync.aligned.m16n8k16.row.col.f32.f16.f16.f32 "
        "{%0,%1,%2,%3},{%4,%5,%6,%7},{%8,%9},{%0,%1,%2,%3};"
        : "+f"(c[0]), "+f"(c[1]), "+f"(c[2]), "+f"(c[3])
        : "r"(a[0]), "r"(a[1]), "r"(a[2]), "r"(a[3]), "r"(b[0]), "r"(b[1]));
}
__device__ __forceinline__ unsigned ld_acq(const unsigned* p) {
    unsigned v;
    asm volatile("ld.acquire.gpu.global.u32 %0, [%1];" : "=r"(v) : "l"(p) : "memory");
    return v;
}
__device__ __forceinline__ void red_rel_add(unsigned* p, unsigned v) {
    asm volatile("red.release.gpu.global.add.u32 [%0], %1;" :: "l"(p), "r"(v) : "memory");
}
__device__ __forceinline__ float fsig(float x) { return __fdividef(1.f, 1.f + __expf(-x)); }

// ---------------- K0: reset per-launch state ----------------
__global__ void reset_kernel() {
    int i = blockIdx.x * blockDim.x + threadIdx.x;
    if (i == 0) g_bar = 0u;
    if (i < BS_) g_energy[i] = 0.f;
}

// ---------------- K1: fp32 -> fp16 weight conversions ----------------
__global__ void convert_kernel(const float* __restrict__ Wg, const float* __restrict__ Wa) {
    size_t i0 = (size_t)blockIdx.x * blockDim.x + threadIdx.x;
    size_t stride = (size_t)gridDim.x * blockDim.x;
    for (size_t i = i0; i < (size_t)G4 * EMBED; i += stride) {
        int n = (int)(i >> 9), k = (int)(i & 511);
        g_Wx16[i] = __float2half_rn(Wg[(size_t)n * 1536 + k]);
    }
    for (size_t i = i0; i < (size_t)G4 * HID; i += stride) {
        int pos = (int)(i >> 10), k = (int)(i & 1023);
        int cta = pos >> 5, q = (pos >> 3) & 3, e = pos & 7;
        int n = (q << 10) + (cta << 3) + e;                 // original Wg row
        g_Wh16[i] = __float2half_rn(Wg[(size_t)n * 1536 + 512 + k]);
    }
    for (size_t i = i0; i < (size_t)HID * HID; i += stride)
        g_Wa16[i] = __float2half_rn(Wa[i]);
}

// ---------------- K2: gather embeddings to fp16, row = t*64+b ----------------
__global__ void gather_kernel(const int* __restrict__ x, const float* __restrict__ emb) {
    size_t i = (size_t)blockIdx.x * blockDim.x + threadIdx.x;   // over BS_*256 half2
    if (i >= (size_t)BS_ * 256) return;
    int r = (int)(i >> 8), k2 = (int)(i & 255);
    int b = r & 63, t = r >> 6;
    int tok = x[b * 512 + t];
    float2 v = ((const float2*)emb)[(size_t)tok * 256 + k2];
    ((half2*)g_E16)[i] = __floats2half2_rn(v.x, v.y);
}

// ---------------- K3/K5: generic mma GEMM, 128x64 block, 8 warps ----------------
// MODE 0: C = E16 @ Wx16^T (+bg), store fp16 to g_Xc with scan-permuted columns. K=512.
// MODE 1: T = hs @ Wa16^T; epilogue sum_n tanh(T)*va[n] -> atomicAdd g_energy[row]. K=1024.
template<int MODE, int K>
__global__ void gemm_kernel(const float* __restrict__ aux) {
    __shared__ __half As[128 * 40];
    __shared__ __half Bs[64 * 40];
    const __half* __restrict__ A = (MODE == 0) ? g_E16 : g_hs;
    const __half* __restrict__ Bm = (MODE == 0) ? g_Wx16 : g_Wa16;

    int tid = threadIdx.x;
    int warp = tid >> 5, lane = tid & 31;
    int wm = warp & 3, wn = warp >> 2;                      // 4x2 warp grid
    int grp = lane >> 2, c0 = (lane & 3) * 2;
    int bm = blockIdx.y, bn = blockIdx.x;

    float acc[2][4][4];
    #pragma unroll
    for (int a = 0; a < 2; a++)
        #pragma unroll
        for (int b = 0; b < 4; b++)
            #pragma unroll
            for (int c = 0; c < 4; c++) acc[a][b][c] = 0.f;

    int seg = tid & 3, r0 = tid >> 2;
    #pragma unroll 1
    for (int kb = 0; kb < K / 32; kb++) {
        *(uint4*)&As[r0 * 40 + seg * 8] =
            *(const uint4*)&A[(size_t)(bm * 128 + r0) * K + kb * 32 + seg * 8];
        *(uint4*)&As[(r0 + 64) * 40 + seg * 8] =
            *(const uint4*)&A[(size_t)(bm * 128 + r0 + 64) * K + kb * 32 + seg * 8];
        *(uint4*)&Bs[r0 * 40 + seg * 8] =
            *(const uint4*)&Bm[(size_t)(bn * 64 + r0) * K + kb * 32 + seg * 8];
        __syncthreads();
        #pragma unroll
        for (int kk = 0; kk < 32; kk += 16) {
            unsigned af[2][4];
            #pragma unroll
            for (int mf = 0; mf < 2; mf++)
                ldmx4(af[mf], &As[(wm * 32 + mf * 16 + (lane & 15)) * 40 + kk + ((lane >> 4) << 3)]);
            unsigned bf[4][2];
            #pragma unroll
            for (int hb = 0; hb < 2; hb++) {
                unsigned r[4];
                int n = wn * 32 + hb * 16 + ((lane >> 4) << 3) + (lane & 7);
                int kq = kk + (((lane >> 3) & 1) << 3);
                ldmx4(r, &Bs[n * 40 + kq]);
                bf[hb * 2 + 0][0] = r[0]; bf[hb * 2 + 0][1] = r[1];
                bf[hb * 2 + 1][0] = r[2]; bf[hb * 2 + 1][1] = r[3];
            }
            #pragma unroll
            for (int mf = 0; mf < 2; mf++)
                #pragma unroll
                for (int nf = 0; nf < 4; nf++)
                    mma16816(acc[mf][nf], af[mf], bf[nf]);
        }
        __syncthreads();
    }

    if (MODE == 0) {
        #pragma unroll
        for (int mf = 0; mf < 2; mf++)
            #pragma unroll
            for (int rp = 0; rp < 2; rp++) {
                int rg = bm * 128 + wm * 32 + mf * 16 + grp + rp * 8;
                #pragma unroll
                for (int nf = 0; nf < 4; nf++) {
                    int n0 = bn * 64 + wn * 32 + nf * 8 + c0;
                    float v0 = acc[mf][nf][rp * 2 + 0] + aux[n0];
                    float v1 = acc[mf][nf][rp * 2 + 1] + aux[n0 + 1];
                    int j = n0 & 1023, q = n0 >> 10;
                    int p = ((j >> 3) << 5) + (q << 3) + (j & 7);
                    *(half2*)&g_Xc[(size_t)rg * G4 + p] = __floats2half2_rn(v0, v1);
                }
            }
    } else {
        #pragma unroll
        for (int mf = 0; mf < 2; mf++)
            #pragma unroll
            for (int rp = 0; rp < 2; rp++) {
                int rg = bm * 128 + wm * 32 + mf * 16 + grp + rp * 8;
                float s = 0.f;
                #pragma unroll
                for (int nf = 0; nf < 4; nf++)
                    #pragma unroll
                    for (int cc = 0; cc < 2; cc++) {
                        int n = bn * 64 + wn * 32 + nf * 8 + c0 + cc;
                        s += tanhf(acc[mf][nf][rp * 2 + cc]) * aux[n];
                    }
                s += __shfl_xor_sync(0xffffffffu, s, 1);
                s += __shfl_xor_sync(0xffffffffu, s, 2);
                if ((lane & 3) == 0) atomicAdd(&g_energy[rg], s);
            }
    }
}

// ---------------- K4: persistent LSTM scan, 128 CTAs x 128 threads ----------------
// CTA k owns hidden dims [k*8, k*8+8) -> 32 gate columns (i,f,g,o blocks of 8).
// Weights (32x1024 fp16) resident in smem for all steps; h_{t-1} staged per step.
__global__ void scan_kernel() {
    extern __shared__ __half sh[];
    __half* Wsm = sh;                 // 32 x 1032
    __half* Hsm = sh + 32 * 1032;     // 64 x 1032
    int tid = threadIdx.x, cta = blockIdx.x;
    int warp = tid >> 5, lane = tid & 31;
    int grp = lane >> 2, c0 = (lane & 3) * 2;
    int rowb = warp * 16;

    for (int i = tid; i < 32 * 128; i += 128) {
        int r = i >> 7, s = i & 127;
        *(uint4*)&Wsm[r * 1032 + s * 8] =
            *(const uint4*)&g_Wh16[((size_t)cta * 32 + r) * 1024 + s * 8];
    }

    float cc[4] = {0.f, 0.f, 0.f, 0.f};   // cell state for this thread's 2 rows x 2 cols

    for (int t = 0; t < S_; t++) {
        if (t > 0) {
            if (tid == 0) {
                unsigned target = (unsigned)(NCTA * t);
                while (ld_acq(&g_bar) < target) __nanosleep(40);
            }
            __syncthreads();
            const __half* hp = &g_hs[(size_t)(t - 1) * 64 * 1024];
            for (int i = tid; i < 64 * 128; i += 128) {
                int r = i >> 7, s = i & 127;
                *(uint4*)&Hsm[r * 1032 + s * 8] = *(const uint4*)&hp[r * 1024 + s * 8];
            }
            __syncthreads();
        }

        float acc[4][4];
        #pragma unroll
        for (int a = 0; a < 4; a++)
            #pragma unroll
            for (int b = 0; b < 4; b++) acc[a][b] = 0.f;

        if (t > 0) {
            #pragma unroll 4
            for (int kk = 0; kk < 1024; kk += 16) {
                unsigned af[4];
                ldmx4(af, &Hsm[(rowb + (lane & 15)) * 1032 + kk + ((lane >> 4) << 3)]);
                unsigned bf[4][2];
                #pragma unroll
                for (int hb = 0; hb < 2; hb++) {
                    unsigned r[4];
                    int n = hb * 16 + ((lane >> 4) << 3) + (lane & 7);
                    int kq = kk + (((lane >> 3) & 1) << 3);
                    ldmx4(r, &Wsm[n * 1032 + kq]);
                    bf[hb * 2 + 0][0] = r[0]; bf[hb * 2 + 0][1] = r[1];
                    bf[hb * 2 + 1][0] = r[2]; bf[hb * 2 + 1][1] = r[3];
                }
                #pragma unroll
                for (int nf = 0; nf < 4; nf++) mma16816(acc[nf], af, bf[nf]);
            }
        }

        // epilogue: gates -> cell update -> h
        #pragma unroll
        for (int rp = 0; rp < 2; rp++) {
            int b = rowb + grp + rp * 8;                    // batch row
            size_t xrow = ((size_t)t * 64 + b) * G4 + (size_t)cta * 32;
            half2 xq[4];
            #pragma unroll
            for (int q = 0; q < 4; q++) xq[q] = *(const half2*)&g_Xc[xrow + q * 8 + c0];
            float hv[2];
            #pragma unroll
            for (int u = 0; u < 2; u++) {
                float xi = u ? __high2float(xq[0]) : __low2float(xq[0]);
                float xf = u ? __high2float(xq[1]) : __low2float(xq[1]);
                float xg = u ? __high2float(xq[2]) : __low2float(xq[2]);
                float xo = u ? __high2float(xq[3]) : __low2float(xq[3]);
                float iv = fsig(acc[0][rp * 2 + u] + xi);
                float fv = fsig(acc[1][rp * 2 + u] + xf);
                float gv = tanhf(acc[2][rp * 2 + u] + xg);
                float ov = fsig(acc[3][rp * 2 + u] + xo);
                float& cs = cc[rp * 2 + u];
                cs = fv * cs + iv * gv;
                hv[u] = ov * tanhf(cs);
            }
            *(half2*)&g_hs[((size_t)t * 64 + b) * 1024 + cta * 8 + c0] =
                __floats2half2_rn(hv[0], hv[1]);
        }

        __threadfence();
        __syncthreads();
        if (tid == 0) red_rel_add(&g_bar, 1u);
    }
}

// ---------------- K6: masked softmax + context ----------------
__global__ void attn_kernel(const int* __restrict__ x) {
    __shared__ float sa[512];
    __shared__ float red[512];
    int b = blockIdx.x, tid = threadIdx.x;
    float e = g_energy[tid * 64 + b];
    if (x[b * 512 + tid] == 0) e = -1e10f;
    red[tid] = e; __syncthreads();
    for (int s = 256; s > 0; s >>= 1) {
        if (tid < s) red[tid] = fmaxf(red[tid], red[tid + s]);
        __syncthreads();
    }
    float mx = red[0]; __syncthreads();
    float ex = __expf(e - mx);
    red[tid] = ex; __syncthreads();
    for (int s = 256; s > 0; s >>= 1) {
        if (tid < s) red[tid] += red[tid + s];
        __syncthreads();
    }
    float inv = __fdividef(1.f, red[0]);
    sa[tid] = ex * inv;
    __syncthreads();
    for (int d = tid; d < HID; d += 512) {
        float s0 = 0.f, s1 = 0.f, s2 = 0.f, s3 = 0.f;
        #pragma unroll 4
        for (int t = 0; t < 512; t += 4) {
            s0 += sa[t + 0] * __half2float(g_hs[((size_t)(t + 0) * 64 + b) * 1024 + d]);
            s1 += sa[t + 1] * __half2float(g_hs[((size_t)(t + 1) * 64 + b) * 1024 + d]);
            s2 += sa[t + 2] * __half2float(g_hs[((size_t)(t + 2) * 64 + b) * 1024 + d]);
            s3 += sa[t + 3] * __half2float(g_hs[((size_t)(t + 3) * 64 + b) * 1024 + d]);
        }
        g_ctx[b * HID + d] = (s0 + s1) + (s2 + s3);
    }
}

// ---------------- K7: final classifier (fp32) ----------------
__global__ void final_kernel(const float* __restrict__ WV, const float* __restrict__ bV,
                             float* __restrict__ out) {
    int i = blockIdx.x * blockDim.x + threadIdx.x;
    if (i >= B_ * NCLS) return;
    int b = i / NCLS, n = i % NCLS;
    const float* c = &g_ctx[b * HID];
    const float* w = &WV[n * HID];
    float s = bV[n];
    #pragma unroll 8
    for (int k = 0; k < HID; k++) s += c[k] * w[k];
    out[i] = s;
}

// ---------------- launch ----------------
extern "C" void kernel_launch(void* const* d_in, const int* in_sizes, int n_in,
                              void* d_out, int out_size) {
    const int*   x   = (const int*)  d_in[0];
    const float* emb = (const float*)d_in[1];
    const float* Wg  = (const float*)d_in[2];
    const float* bg  = (const float*)d_in[3];
    const float* Wa  = (const float*)d_in[4];
    const float* va  = (const float*)d_in[5];
    const float* WV  = (const float*)d_in[6];
    const float* bV  = (const float*)d_in[7];
    float* out = (float*)d_out;
    (void)Wg; (void)n_in; (void)in_sizes; (void)out_size;

    reset_kernel<<<128, 256>>>();
    convert_kernel<<<2048, 256>>>(Wg, Wa);
    gather_kernel<<<BS_, 256>>>(x, emb);

    gemm_kernel<0, 512><<<dim3(G4 / 64, BS_ / 128), 256>>>(bg);

    const int smem_scan = (32 * 1032 + 64 * 1032) * (int)sizeof(__half);  // 198144
    cudaFuncSetAttribute(scan_kernel, cudaFuncAttributeMaxDynamicSharedMemorySize, smem_scan);
    scan_kernel<<<NCTA, 128, smem_scan>>>();

    gemm_kernel<1, 1024><<<dim3(HID / 64, BS_ / 128), 256>>>(va);

    attn_kernel<<<B_, 512>>>(x);
    final_kernel<<<3, 256>>>(WV, bV, out);
}

// round 3
// speedup vs baseline: 1.7354x; 1.7354x over previous
#include <cuda_runtime.h>
#include <cuda_fp16.h>
#include <cstdint>

#define VOCAB 50257
#define EMBED 512
#define HID   1024
#define G4    4096
#define NCLS  10
#define B_    64
#define S_    512
#define BS_   (B_*S_)
#define NCTA  128

// ---------------- device scratch (no allocations allowed) ----------------
__device__ __half  g_E16[(size_t)BS_*EMBED];    // gathered embeddings, row r = t*64+b
__device__ __half  g_Wx16[(size_t)G4*EMBED];    // Wg[:, :512] fp16
__device__ __half  g_Wh16[(size_t)G4*HID];      // Wg[:, 512:] fp16, scan-permuted rows
__device__ __half  g_Wa16[(size_t)HID*HID];
__device__ __half  g_Xc [(size_t)BS_*G4];       // x-part of gates (+bg), scan-permuted cols
__device__ __half  g_hs [(size_t)BS_*HID];      // all hidden states, row r = t*64+b
__device__ float   g_energy[BS_];
__device__ float   g_ctx[B_*HID];
__device__ unsigned g_bar;

// ---------------- helpers ----------------
__device__ __forceinline__ void ldmx4(unsigned r[4], const void* p) {
    unsigned a = (unsigned)__cvta_generic_to_shared(p);
    asm volatile("ldmatrix.sync.aligned.m8n8.x4.shared.b16 {%0,%1,%2,%3}, [%4];"
        : "=r"(r[0]), "=r"(r[1]), "=r"(r[2]), "=r"(r[3]) : "r"(a));
}
__device__ __forceinline__ void mma16816(float* c, const unsigned* a, const unsigned* b) {
    asm volatile("mma.sync.aligned.m16n8k16.row.col.f32.f16.f16.f32 "
        "{%0,%1,%2,%3},{%4,%5,%6,%7},{%8,%9},{%0,%1,%2,%3};"
        : "+f"(c[0]), "+f"(c[1]), "+f"(c[2]), "+f"(c[3])
        : "r"(a[0]), "r"(a[1]), "r"(a[2]), "r"(a[3]), "r"(b[0]), "r"(b[1]));
}
__device__ __forceinline__ unsigned ld_acq(const unsigned* p) {
    unsigned v;
    asm volatile("ld.acquire.gpu.global.u32 %0, [%1];" : "=r"(v) : "l"(p) : "memory");
    return v;
}
__device__ __forceinline__ void red_rel_add(unsigned* p, unsigned v) {
    asm volatile("red.release.gpu.global.add.u32 [%0], %1;" :: "l"(p), "r"(v) : "memory");
}
__device__ __forceinline__ void cp16(void* dst, const void* src) {
    unsigned d = (unsigned)__cvta_generic_to_shared(dst);
    asm volatile("cp.async.cg.shared.global [%0], [%1], 16;" :: "r"(d), "l"(src));
}
__device__ __forceinline__ float fsig(float x) { return __fdividef(1.f, 1.f + __expf(-x)); }
__device__ __forceinline__ float ftanh(float x) { return 2.f * fsig(2.f * x) - 1.f; }

// ---------------- K0: reset per-launch state ----------------
__global__ void reset_kernel() {
    int i = blockIdx.x * blockDim.x + threadIdx.x;
    if (i == 0) g_bar = 0u;
    if (i < BS_) g_energy[i] = 0.f;
}

// ---------------- K1: fp32 -> fp16 weight conversions ----------------
__global__ void convert_kernel(const float* __restrict__ Wg, const float* __restrict__ Wa) {
    size_t i0 = (size_t)blockIdx.x * blockDim.x + threadIdx.x;
    size_t stride = (size_t)gridDim.x * blockDim.x;
    for (size_t i = i0; i < (size_t)G4 * EMBED; i += stride) {
        int n = (int)(i >> 9), k = (int)(i & 511);
        g_Wx16[i] = __float2half_rn(Wg[(size_t)n * 1536 + k]);
    }
    for (size_t i = i0; i < (size_t)G4 * HID; i += stride) {
        int pos = (int)(i >> 10), k = (int)(i & 1023);
        int cta = pos >> 5, q = (pos >> 3) & 3, e = pos & 7;
        int n = (q << 10) + (cta << 3) + e;                 // original Wg row
        g_Wh16[i] = __float2half_rn(Wg[(size_t)n * 1536 + 512 + k]);
    }
    for (size_t i = i0; i < (size_t)HID * HID; i += stride)
        g_Wa16[i] = __float2half_rn(Wa[i]);
}

// ---------------- K2: gather embeddings to fp16, row = t*64+b ----------------
__global__ void gather_kernel(const int* __restrict__ x, const float* __restrict__ emb) {
    size_t i = (size_t)blockIdx.x * blockDim.x + threadIdx.x;   // over BS_*256 half2
    if (i >= (size_t)BS_ * 256) return;
    int r = (int)(i >> 8), k2 = (int)(i & 255);
    int b = r & 63, t = r >> 6;
    int tok = x[b * 512 + t];
    float2 v = ((const float2*)emb)[(size_t)tok * 256 + k2];
    ((half2*)g_E16)[i] = __floats2half2_rn(v.x, v.y);
}

// ---------------- K3/K5: generic mma GEMM, 128x64 block, 8 warps ----------------
template<int MODE, int K>
__global__ void gemm_kernel(const float* __restrict__ aux) {
    __shared__ __half As[128 * 40];
    __shared__ __half Bs[64 * 40];
    const __half* __restrict__ A = (MODE == 0) ? g_E16 : g_hs;
    const __half* __restrict__ Bm = (MODE == 0) ? g_Wx16 : g_Wa16;

    int tid = threadIdx.x;
    int warp = tid >> 5, lane = tid & 31;
    int wm = warp & 3, wn = warp >> 2;                      // 4x2 warp grid
    int grp = lane >> 2, c0 = (lane & 3) * 2;
    int bm = blockIdx.y, bn = blockIdx.x;

    float acc[2][4][4];
    #pragma unroll
    for (int a = 0; a < 2; a++)
        #pragma unroll
        for (int b = 0; b < 4; b++)
            #pragma unroll
            for (int c = 0; c < 4; c++) acc[a][b][c] = 0.f;

    int seg = tid & 3, r0 = tid >> 2;
    #pragma unroll 1
    for (int kb = 0; kb < K / 32; kb++) {
        *(uint4*)&As[r0 * 40 + seg * 8] =
            *(const uint4*)&A[(size_t)(bm * 128 + r0) * K + kb * 32 + seg * 8];
        *(uint4*)&As[(r0 + 64) * 40 + seg * 8] =
            *(const uint4*)&A[(size_t)(bm * 128 + r0 + 64) * K + kb * 32 + seg * 8];
        *(uint4*)&Bs[r0 * 40 + seg * 8] =
            *(const uint4*)&Bm[(size_t)(bn * 64 + r0) * K + kb * 32 + seg * 8];
        __syncthreads();
        #pragma unroll
        for (int kk = 0; kk < 32; kk += 16) {
            unsigned af[2][4];
            #pragma unroll
            for (int mf = 0; mf < 2; mf++)
                ldmx4(af[mf], &As[(wm * 32 + mf * 16 + (lane & 15)) * 40 + kk + ((lane >> 4) << 3)]);
            unsigned bf[4][2];
            #pragma unroll
            for (int hb = 0; hb < 2; hb++) {
                unsigned r[4];
                int n = wn * 32 + hb * 16 + ((lane >> 4) << 3) + (lane & 7);
                int kq = kk + (((lane >> 3) & 1) << 3);
                ldmx4(r, &Bs[n * 40 + kq]);
                bf[hb * 2 + 0][0] = r[0]; bf[hb * 2 + 0][1] = r[1];
                bf[hb * 2 + 1][0] = r[2]; bf[hb * 2 + 1][1] = r[3];
            }
            #pragma unroll
            for (int mf = 0; mf < 2; mf++)
                #pragma unroll
                for (int nf = 0; nf < 4; nf++)
                    mma16816(acc[mf][nf], af[mf], bf[nf]);
        }
        __syncthreads();
    }

    if (MODE == 0) {
        #pragma unroll
        for (int mf = 0; mf < 2; mf++)
            #pragma unroll
            for (int rp = 0; rp < 2; rp++) {
                int rg = bm * 128 + wm * 32 + mf * 16 + grp + rp * 8;
                #pragma unroll
                for (int nf = 0; nf < 4; nf++) {
                    int n0 = bn * 64 + wn * 32 + nf * 8 + c0;
                    float v0 = acc[mf][nf][rp * 2 + 0] + aux[n0];
                    float v1 = acc[mf][nf][rp * 2 + 1] + aux[n0 + 1];
                    int j = n0 & 1023, q = n0 >> 10;
                    int p = ((j >> 3) << 5) + (q << 3) + (j & 7);
                    *(half2*)&g_Xc[(size_t)rg * G4 + p] = __floats2half2_rn(v0, v1);
                }
            }
    } else {
        #pragma unroll
        for (int mf = 0; mf < 2; mf++)
            #pragma unroll
            for (int rp = 0; rp < 2; rp++) {
                int rg = bm * 128 + wm * 32 + mf * 16 + grp + rp * 8;
                float s = 0.f;
                #pragma unroll
                for (int nf = 0; nf < 4; nf++)
                    #pragma unroll
                    for (int cc = 0; cc < 2; cc++) {
                        int n = bn * 64 + wn * 32 + nf * 8 + c0 + cc;
                        s += ftanh(acc[mf][nf][rp * 2 + cc]) * aux[n];
                    }
                s += __shfl_xor_sync(0xffffffffu, s, 1);
                s += __shfl_xor_sync(0xffffffffu, s, 2);
                if ((lane & 3) == 0) atomicAdd(&g_energy[rg], s);
            }
    }
}

// ---------------- K4: persistent LSTM scan, 128 CTAs x 256 threads ----------------
// CTA k owns hidden dims [k*8, k*8+8) -> 32 gate columns (i,f,g,o blocks of 8).
// Warps 0-3 (group 0) compute K in [0,512); warps 4-7 (group 1) compute K in [512,1024).
// Partial accumulators reduced through smem; group 0 does the pointwise cell update.
__global__ void scan_kernel() {
    extern __shared__ __half sh[];
    __half* Wsm = sh;                              // 32 x 1032
    __half* Hsm = sh + 32 * 1032;                  // 64 x 1032
    float*  Rsm = (float*)(sh + 32 * 1032 + 64 * 1032);  // 128*17 floats
    int tid = threadIdx.x, cta = blockIdx.x;
    int warp = tid >> 5, lane = tid & 31;
    int wg = warp >> 2, wm = warp & 3;             // group, row-block
    int gtid = tid & 127;
    int grp = lane >> 2, c0 = (lane & 3) * 2;
    int rowb = wm * 16;
    int kbase = wg * 512;

    for (int i = tid; i < 32 * 128; i += 256) {
        int r = i >> 7, s = i & 127;
        *(uint4*)&Wsm[r * 1032 + s * 8] =
            *(const uint4*)&g_Wh16[((size_t)cta * 32 + r) * 1024 + s * 8];
    }

    float cc[4] = {0.f, 0.f, 0.f, 0.f};
    int ridx = (wm * 32 + lane) * 17;

    for (int t = 0; t < S_; t++) {
        // prefetch the x-part of the gates (independent of h_{t-1}) under the barrier wait
        half2 xq[2][4];
        if (wg == 0) {
            #pragma unroll
            for (int rp = 0; rp < 2; rp++) {
                int b = rowb + grp + rp * 8;
                size_t xrow = ((size_t)t * 64 + b) * G4 + (size_t)cta * 32;
                #pragma unroll
                for (int q = 0; q < 4; q++)
                    xq[rp][q] = *(const half2*)&g_Xc[xrow + q * 8 + c0];
            }
        }

        float acc[4][4];
        #pragma unroll
        for (int a = 0; a < 4; a++)
            #pragma unroll
            for (int b = 0; b < 4; b++) acc[a][b] = 0.f;

        if (t > 0) {
            if (tid == 0) {
                unsigned target = (unsigned)(NCTA * t);
                while (ld_acq(&g_bar) < target) __nanosleep(40);
            }
            __syncthreads();

            // each group stages its own 64KB K-half of h_{t-1} via cp.async (L2-direct)
            const __half* hp = &g_hs[(size_t)(t - 1) * 64 * 1024];
            #pragma unroll 8
            for (int i = gtid; i < 4096; i += 128) {
                int r = i >> 6, s = i & 63;
                cp16(&Hsm[r * 1032 + kbase + s * 8], &hp[r * 1024 + kbase + s * 8]);
            }
            asm volatile("cp.async.commit_group;");
            asm volatile("cp.async.wait_group 0;");
            asm volatile("bar.sync %0, %1;" :: "r"(wg + 1), "r"(128));

            #pragma unroll 4
            for (int kk = 0; kk < 512; kk += 16) {
                unsigned af[4];
                ldmx4(af, &Hsm[(rowb + (lane & 15)) * 1032 + kbase + kk + ((lane >> 4) << 3)]);
                unsigned bf[4][2];
                #pragma unroll
                for (int hb = 0; hb < 2; hb++) {
                    unsigned r[4];
                    int n = hb * 16 + ((lane >> 4) << 3) + (lane & 7);
                    int kq = kk + (((lane >> 3) & 1) << 3);
                    ldmx4(r, &Wsm[n * 1032 + kbase + kq]);
                    bf[hb * 2 + 0][0] = r[0]; bf[hb * 2 + 0][1] = r[1];
                    bf[hb * 2 + 1][0] = r[2]; bf[hb * 2 + 1][1] = r[3];
                }
                #pragma unroll
                for (int nf = 0; nf < 4; nf++) mma16816(acc[nf], af, bf[nf]);
            }
        }

        // cross-group reduction of partial accumulators
        if (wg == 1) {
            #pragma unroll
            for (int j = 0; j < 16; j++) Rsm[ridx + j] = acc[j >> 2][j & 3];
        }
        __syncthreads();

        if (wg == 0) {
            #pragma unroll
            for (int j = 0; j < 16; j++) acc[j >> 2][j & 3] += Rsm[ridx + j];

            // gates -> cell update -> h
            #pragma unroll
            for (int rp = 0; rp < 2; rp++) {
                int b = rowb + grp + rp * 8;
                float hv[2];
                #pragma unroll
                for (int u = 0; u < 2; u++) {
                    float xi = u ? __high2float(xq[rp][0]) : __low2float(xq[rp][0]);
                    float xf = u ? __high2float(xq[rp][1]) : __low2float(xq[rp][1]);
                    float xg = u ? __high2float(xq[rp][2]) : __low2float(xq[rp][2]);
                    float xo = u ? __high2float(xq[rp][3]) : __low2float(xq[rp][3]);
                    float iv = fsig(acc[0][rp * 2 + u] + xi);
                    float fv = fsig(acc[1][rp * 2 + u] + xf);
                    float gv = ftanh(acc[2][rp * 2 + u] + xg);
                    float ov = fsig(acc[3][rp * 2 + u] + xo);
                    float& cs = cc[rp * 2 + u];
                    cs = fv * cs + iv * gv;
                    hv[u] = ov * ftanh(cs);
                }
                *(half2*)&g_hs[((size_t)t * 64 + b) * 1024 + cta * 8 + c0] =
                    __floats2half2_rn(hv[0], hv[1]);
            }
        }

        __threadfence();
        __syncthreads();
        if (tid == 0) red_rel_add(&g_bar, 1u);
    }
}

// ---------------- K6: masked softmax + context ----------------
__global__ void attn_kernel(const int* __restrict__ x) {
    __shared__ float sa[512];
    __shared__ float red[512];
    int b = blockIdx.x, tid = threadIdx.x;
    float e = g_energy[tid * 64 + b];
    if (x[b * 512 + tid] == 0) e = -1e10f;
    red[tid] = e; __syncthreads();
    for (int s = 256; s > 0; s >>= 1) {
        if (tid < s) red[tid] = fmaxf(red[tid], red[tid + s]);
        __syncthreads();
    }
    float mx = red[0]; __syncthreads();
    float ex = __expf(e - mx);
    red[tid] = ex; __syncthreads();
    for (int s = 256; s > 0; s >>= 1) {
        if (tid < s) red[tid] += red[tid + s];
        __syncthreads();
    }
    float inv = __fdividef(1.f, red[0]);
    sa[tid] = ex * inv;
    __syncthreads();
    for (int d = tid; d < HID; d += 512) {
        float s0 = 0.f, s1 = 0.f, s2 = 0.f, s3 = 0.f;
        #pragma unroll 4
        for (int t = 0; t < 512; t += 4) {
            s0 += sa[t + 0] * __half2float(g_hs[((size_t)(t + 0) * 64 + b) * 1024 + d]);
            s1 += sa[t + 1] * __half2float(g_hs[((size_t)(t + 1) * 64 + b) * 1024 + d]);
            s2 += sa[t + 2] * __half2float(g_hs[((size_t)(t + 2) * 64 + b) * 1024 + d]);
            s3 += sa[t + 3] * __half2float(g_hs[((size_t)(t + 3) * 64 + b) * 1024 + d]);
        }
        g_ctx[b * HID + d] = (s0 + s1) + (s2 + s3);
    }
}

// ---------------- K7: final classifier (fp32) ----------------
__global__ void final_kernel(const float* __restrict__ WV, const float* __restrict__ bV,
                             float* __restrict__ out) {
    int i = blockIdx.x * blockDim.x + threadIdx.x;
    if (i >= B_ * NCLS) return;
    int b = i / NCLS, n = i % NCLS;
    const float* c = &g_ctx[b * HID];
    const float* w = &WV[n * HID];
    float s = bV[n];
    #pragma unroll 8
    for (int k = 0; k < HID; k++) s += c[k] * w[k];
    out[i] = s;
}

// ---------------- launch ----------------
extern "C" void kernel_launch(void* const* d_in, const int* in_sizes, int n_in,
                              void* d_out, int out_size) {
    const int*   x   = (const int*)  d_in[0];
    const float* emb = (const float*)d_in[1];
    const float* Wg  = (const float*)d_in[2];
    const float* bg  = (const float*)d_in[3];
    const float* Wa  = (const float*)d_in[4];
    const float* va  = (const float*)d_in[5];
    const float* WV  = (const float*)d_in[6];
    const float* bV  = (const float*)d_in[7];
    float* out = (float*)d_out;
    (void)n_in; (void)in_sizes; (void)out_size;

    reset_kernel<<<128, 256>>>();
    convert_kernel<<<2048, 256>>>(Wg, Wa);
    gather_kernel<<<BS_, 256>>>(x, emb);

    gemm_kernel<0, 512><<<dim3(G4 / 64, BS_ / 128), 256>>>(bg);

    const int smem_scan = (32 * 1032 + 64 * 1032) * (int)sizeof(__half)
                        + 128 * 17 * (int)sizeof(float);   // 206848
    cudaFuncSetAttribute(scan_kernel, cudaFuncAttributeMaxDynamicSharedMemorySize, smem_scan);
    scan_kernel<<<NCTA, 256, smem_scan>>>();

    gemm_kernel<1, 1024><<<dim3(HID / 64, BS_ / 128), 256>>>(va);

    attn_kernel<<<B_, 512>>>(x);
    final_kernel<<<3, 256>>>(WV, bV, out);
}

// round 4
// speedup vs baseline: 2.0766x; 1.1966x over previous
#include <cuda_runtime.h>
#include <cuda_fp16.h>
#include <cstdint>

#define VOCAB 50257
#define EMBED 512
#define HID   1024
#define G4    4096
#define NCLS  10
#define B_    64
#define S_    512
#define BS_   (B_*S_)
#define NCTA  128

// ---------------- device scratch (no allocations allowed) ----------------
__device__ __half  g_E16[(size_t)BS_*EMBED];    // gathered embeddings, row r = t*64+b
__device__ __half  g_Wx16[(size_t)G4*EMBED];    // Wg[:, :512] fp16
__device__ __half  g_Wh16[(size_t)G4*HID];      // Wg[:, 512:] fp16, scan-permuted rows
__device__ __half  g_Wa16[(size_t)HID*HID];
__device__ __half  g_Xc [(size_t)BS_*G4];       // x-part of gates (+bg), col p = dim*4+gate
__device__ __half  g_hs [(size_t)BS_*HID];      // all hidden states, row r = t*64+b
__device__ float   g_energy[BS_];
__device__ float   g_ctx[B_*HID];
__device__ unsigned g_bar2[64];                 // slot 0 and 32 used (separate lines)

// ---------------- helpers ----------------
__device__ __forceinline__ void ldmx4(unsigned r[4], const void* p) {
    unsigned a = (unsigned)__cvta_generic_to_shared(p);
    asm volatile("ldmatrix.sync.aligned.m8n8.x4.shared.b16 {%0,%1,%2,%3}, [%4];"
        : "=r"(r[0]), "=r"(r[1]), "=r"(r[2]), "=r"(r[3]) : "r"(a));
}
__device__ __forceinline__ void mma16816(float* c, const unsigned* a, const unsigned* b) {
    asm volatile("mma.sync.aligned.m16n8k16.row.col.f32.f16.f16.f32 "
        "{%0,%1,%2,%3},{%4,%5,%6,%7},{%8,%9},{%0,%1,%2,%3};"
        : "+f"(c[0]), "+f"(c[1]), "+f"(c[2]), "+f"(c[3])
        : "r"(a[0]), "r"(a[1]), "r"(a[2]), "r"(a[3]), "r"(b[0]), "r"(b[1]));
}
__device__ __forceinline__ unsigned ld_acq(const unsigned* p) {
    unsigned v;
    asm volatile("ld.acquire.gpu.global.u32 %0, [%1];" : "=r"(v) : "l"(p) : "memory");
    return v;
}
__device__ __forceinline__ void red_rel_add(unsigned* p, unsigned v) {
    asm volatile("red.release.gpu.global.add.u32 [%0], %1;" :: "l"(p), "r"(v) : "memory");
}
__device__ __forceinline__ void cp16(void* dst, const void* src) {
    unsigned d = (unsigned)__cvta_generic_to_shared(dst);
    asm volatile("cp.async.cg.shared.global [%0], [%1], 16;" :: "r"(d), "l"(src));
}
__device__ __forceinline__ float fsig(float x) { return __fdividef(1.f, 1.f + __expf(-x)); }
__device__ __forceinline__ float ftanh(float x) { return 2.f * fsig(2.f * x) - 1.f; }

// ---------------- K0: reset per-launch state ----------------
__global__ void reset_kernel() {
    int i = blockIdx.x * blockDim.x + threadIdx.x;
    if (i < 64) g_bar2[i] = 0u;
    if (i < BS_) g_energy[i] = 0.f;
}

// ---------------- K1: fp32 -> fp16 weight conversions ----------------
__global__ void convert_kernel(const float* __restrict__ Wg, const float* __restrict__ Wa) {
    size_t i0 = (size_t)blockIdx.x * blockDim.x + threadIdx.x;
    size_t stride = (size_t)gridDim.x * blockDim.x;
    for (size_t i = i0; i < (size_t)G4 * EMBED; i += stride) {
        int n = (int)(i >> 9), k = (int)(i & 511);
        g_Wx16[i] = __float2half_rn(Wg[(size_t)n * 1536 + k]);
    }
    // scan layout: row = hc*64 + q*16 + e  <->  original row n = q*1024 + hc*16 + e
    for (size_t i = i0; i < (size_t)G4 * HID; i += stride) {
        int pos = (int)(i >> 10), k = (int)(i & 1023);
        int hc = pos >> 6, q = (pos >> 4) & 3, e = pos & 15;
        int n = (q << 10) + (hc << 4) + e;
        g_Wh16[i] = __float2half_rn(Wg[(size_t)n * 1536 + 512 + k]);
    }
    for (size_t i = i0; i < (size_t)HID * HID; i += stride)
        g_Wa16[i] = __float2half_rn(Wa[i]);
}

// ---------------- K2: gather embeddings to fp16, row = t*64+b ----------------
__global__ void gather_kernel(const int* __restrict__ x, const float* __restrict__ emb) {
    size_t i = (size_t)blockIdx.x * blockDim.x + threadIdx.x;   // over BS_*256 half2
    if (i >= (size_t)BS_ * 256) return;
    int r = (int)(i >> 8), k2 = (int)(i & 255);
    int b = r & 63, t = r >> 6;
    int tok = x[b * 512 + t];
    float2 v = ((const float2*)emb)[(size_t)tok * 256 + k2];
    ((half2*)g_E16)[i] = __floats2half2_rn(v.x, v.y);
}

// ---------------- K3/K5: mma GEMM, 128x128 block, 8 warps (64x32 tiles), cp.async 2-stage ----------------
// MODE 0: C = E16 @ Wx16^T (+bg) -> g_Xc fp16, col permuted p = dim*4+gate. K=512.
// MODE 1: T = hs @ Wa16^T; sum_n tanh(T)*va[n] -> atomicAdd g_energy[row]. K=1024.
template<int MODE, int K>
__global__ void gemm_kernel(const float* __restrict__ aux) {
    __shared__ __half As[2][128 * 40];
    __shared__ __half Bs[2][128 * 40];
    const __half* __restrict__ A  = (MODE == 0) ? g_E16 : g_hs;
    const __half* __restrict__ Bm = (MODE == 0) ? g_Wx16 : g_Wa16;

    int tid = threadIdx.x;
    int warp = tid >> 5, lane = tid & 31;
    int wm = warp >> 2, wn = warp & 3;             // 2x4 warp grid, 64x32 tiles
    int grp = lane >> 2, c0 = (lane & 3) * 2;
    int bm = blockIdx.y, bn = blockIdx.x;

    float acc[4][4][4];
    #pragma unroll
    for (int a = 0; a < 4; a++)
        #pragma unroll
        for (int b = 0; b < 4; b++)
            #pragma unroll
            for (int c = 0; c < 4; c++) acc[a][b][c] = 0.f;

    int seg = tid & 3, r0 = tid >> 2;              // r0 in [0,64)
    const int NK = K / 32;

    auto issue = [&](int kb, int st) {
        cp16(&As[st][r0 * 40 + seg * 8],        &A [(size_t)(bm * 128 + r0)      * K + kb * 32 + seg * 8]);
        cp16(&As[st][(r0 + 64) * 40 + seg * 8], &A [(size_t)(bm * 128 + r0 + 64) * K + kb * 32 + seg * 8]);
        cp16(&Bs[st][r0 * 40 + seg * 8],        &Bm[(size_t)(bn * 128 + r0)      * K + kb * 32 + seg * 8]);
        cp16(&Bs[st][(r0 + 64) * 40 + seg * 8], &Bm[(size_t)(bn * 128 + r0 + 64) * K + kb * 32 + seg * 8]);
        asm volatile("cp.async.commit_group;");
    };

    issue(0, 0);
    #pragma unroll 1
    for (int kb = 0; kb < NK; kb++) {
        asm volatile("cp.async.wait_group 0;");
        __syncthreads();
        if (kb + 1 < NK) issue(kb + 1, (kb + 1) & 1);
        const __half* as = As[kb & 1];
        const __half* bs = Bs[kb & 1];
        #pragma unroll
        for (int kk = 0; kk < 32; kk += 16) {
            unsigned af[4][4];
            #pragma unroll
            for (int mf = 0; mf < 4; mf++)
                ldmx4(af[mf], &as[(wm * 64 + mf * 16 + (lane & 15)) * 40 + kk + ((lane >> 4) << 3)]);
            unsigned bf[4][2];
            #pragma unroll
            for (int hb = 0; hb < 2; hb++) {
                unsigned r[4];
                int n = wn * 32 + hb * 16 + ((lane >> 4) << 3) + (lane & 7);
                int kq = kk + (((lane >> 3) & 1) << 3);
                ldmx4(r, &bs[n * 40 + kq]);
                bf[hb * 2 + 0][0] = r[0]; bf[hb * 2 + 0][1] = r[1];
                bf[hb * 2 + 1][0] = r[2]; bf[hb * 2 + 1][1] = r[3];
            }
            #pragma unroll
            for (int mf = 0; mf < 4; mf++)
                #pragma unroll
                for (int nf = 0; nf < 4; nf++)
                    mma16816(acc[mf][nf], af[mf], bf[nf]);
        }
        __syncthreads();
    }

    if (MODE == 0) {
        #pragma unroll
        for (int mf = 0; mf < 4; mf++)
            #pragma unroll
            for (int rp = 0; rp < 2; rp++) {
                int rg = bm * 128 + wm * 64 + mf * 16 + grp + rp * 8;
                #pragma unroll
                for (int nf = 0; nf < 4; nf++) {
                    int n0 = bn * 128 + wn * 32 + nf * 8 + c0;
                    float v0 = acc[mf][nf][rp * 2 + 0] + aux[n0];
                    float v1 = acc[mf][nf][rp * 2 + 1] + aux[n0 + 1];
                    int q = n0 >> 10, d = n0 & 1023;
                    g_Xc[(size_t)rg * G4 + d * 4 + q]       = __float2half_rn(v0);
                    g_Xc[(size_t)rg * G4 + (d + 1) * 4 + q] = __float2half_rn(v1);
                }
            }
    } else {
        #pragma unroll
        for (int mf = 0; mf < 4; mf++)
            #pragma unroll
            for (int rp = 0; rp < 2; rp++) {
                int rg = bm * 128 + wm * 64 + mf * 16 + grp + rp * 8;
                float s = 0.f;
                #pragma unroll
                for (int nf = 0; nf < 4; nf++)
                    #pragma unroll
                    for (int cc = 0; cc < 2; cc++) {
                        int n = bn * 128 + wn * 32 + nf * 8 + c0 + cc;
                        s += ftanh(acc[mf][nf][rp * 2 + cc]) * aux[n];
                    }
                s += __shfl_xor_sync(0xffffffffu, s, 1);
                s += __shfl_xor_sync(0xffffffffu, s, 2);
                if ((lane & 3) == 0) atomicAdd(&g_energy[rg], s);
            }
    }
}

// ---------------- K4: persistent LSTM scan, 2 batch groups x 64 hidden-CTAs ----------------
// CTA (bg,hc): batch rows [bg*32, bg*32+32), hidden dims [hc*16, hc*16+16) -> 64 gate cols.
// Wh slice (64x1024 fp16 = 132KB padded) resident in smem; h tile 32x1024 staged per step.
// 8 warps: wm in {0,1} (16 rows), wk in [0,4) (K chunk of 256). Partials reduced via smem
// Psum (aliased into Hsm). Fixed thread->(row,dim) epilogue keeps cell state in registers.
__global__ void scan_kernel() {
    extern __shared__ __half sh[];
    __half* Wsm = sh;                              // 64 x 1032
    __half* Hsm = sh + 64 * 1032;                  // 32 x 1032
    float*  Psf = (float*)Hsm;                     // alias: [4][32][68] fp32 (34.8KB < 66KB)
    int tid = threadIdx.x, cta = blockIdx.x;
    int warp = tid >> 5, lane = tid & 31;
    int wk = warp >> 1, wm = warp & 1;
    int grp = lane >> 2, c0 = (lane & 3) * 2;
    int bg = cta >> 6, hc = cta & 63;
    int kbase = wk * 256;
    unsigned* bar = &g_bar2[bg * 32];

    // resident weights: rows hc*64 .. hc*64+64 of scan-permuted Wh
    for (int i = tid; i < 64 * 128; i += 256) {
        int r = i >> 7, s = i & 127;
        *(uint4*)&Wsm[r * 1032 + s * 8] =
            *(const uint4*)&g_Wh16[((size_t)hc * 64 + r) * 1024 + s * 8];
    }

    int m = tid >> 3, e0 = (tid & 7) * 2;          // epilogue ownership: row m, dims e0,e0+1
    int rowg = bg * 32 + m;
    float cc0 = 0.f, cc1 = 0.f;

    for (int t = 0; t < S_; t++) {
        // prefetch x-part of gates (independent of h_{t-1}): 4 gates x 2 dims = 8 halves
        uint4 xq = *(const uint4*)&g_Xc[((size_t)t * 64 + rowg) * G4 + (hc * 16 + e0) * 4];

        if (t > 0) {
            if (tid == 0) {
                unsigned target = 64u * (unsigned)t;
                while (ld_acq(bar) < target) {}
            }
            __syncthreads();
            // stage this group's 32 rows of h_{t-1} (64KB) via cp.async (L2-direct)
            const __half* hp = &g_hs[((size_t)(t - 1) * 64 + bg * 32) * 1024];
            #pragma unroll
            for (int i = 0; i < 16; i++) {
                int idx = tid + i * 256;           // 0..4095 16B chunks
                int r = idx >> 7, s = idx & 127;
                cp16(&Hsm[r * 1032 + s * 8], &hp[r * 1024 + s * 8]);
            }
            asm volatile("cp.async.commit_group;");
            asm volatile("cp.async.wait_group 0;");
            __syncthreads();
        }

        float acc[8][4];
        #pragma unroll
        for (int a = 0; a < 8; a++)
            #pragma unroll
            for (int b = 0; b < 4; b++) acc[a][b] = 0.f;

        if (t > 0) {
            #pragma unroll 2
            for (int kk = 0; kk < 256; kk += 16) {
                unsigned af[4];
                ldmx4(af, &Hsm[(wm * 16 + (lane & 15)) * 1032 + kbase + kk + ((lane >> 4) << 3)]);
                unsigned bf[8][2];
                #pragma unroll
                for (int hb = 0; hb < 4; hb++) {
                    unsigned r[4];
                    int n = hb * 16 + ((lane >> 4) << 3) + (lane & 7);
                    int kq = kk + (((lane >> 3) & 1) << 3);
                    ldmx4(r, &Wsm[n * 1032 + kbase + kq]);
                    bf[hb * 2 + 0][0] = r[0]; bf[hb * 2 + 0][1] = r[1];
                    bf[hb * 2 + 1][0] = r[2]; bf[hb * 2 + 1][1] = r[3];
                }
                #pragma unroll
                for (int nf = 0; nf < 8; nf++) mma16816(acc[nf], af, bf[nf]);
            }
        }

        __syncthreads();   // all Hsm reads done before Psum (alias) overwrite
        #pragma unroll
        for (int nf = 0; nf < 8; nf++)
            #pragma unroll
            for (int rp = 0; rp < 2; rp++) {
                int mm = wm * 16 + grp + rp * 8;
                *(float2*)&Psf[(wk * 32 + mm) * 68 + nf * 8 + c0] =
                    make_float2(acc[nf][rp * 2 + 0], acc[nf][rp * 2 + 1]);
            }
        __syncthreads();

        // cell update: this thread owns (row m, dims e0,e0+1)
        const __half* xh = (const __half*)&xq;
        float h0, h1;
        #pragma unroll
        for (int j = 0; j < 2; j++) {
            int e = e0 + j;
            float gq[4];
            #pragma unroll
            for (int q = 0; q < 4; q++) {
                float s = 0.f;
                #pragma unroll
                for (int k = 0; k < 4; k++) s += Psf[(k * 32 + m) * 68 + q * 16 + e];
                gq[q] = s + __half2float(xh[j * 4 + q]);
            }
            float iv = fsig(gq[0]), fv = fsig(gq[1]);
            float gv = ftanh(gq[2]), ov = fsig(gq[3]);
            float& cs = j ? cc1 : cc0;
            cs = fv * cs + iv * gv;
            float hv = ov * ftanh(cs);
            if (j == 0) h0 = hv; else h1 = hv;
        }
        *(half2*)&g_hs[((size_t)t * 64 + rowg) * 1024 + hc * 16 + e0] =
            __floats2half2_rn(h0, h1);

        __syncthreads();                 // all STG issued before leader's release
        if (tid == 0) red_rel_add(bar, 1u);
    }
}

// ---------------- K6: masked softmax + context ----------------
__global__ void attn_kernel(const int* __restrict__ x) {
    __shared__ float sa[512];
    __shared__ float red[512];
    int b = blockIdx.x, tid = threadIdx.x;
    float e = g_energy[tid * 64 + b];
    if (x[b * 512 + tid] == 0) e = -1e10f;
    red[tid] = e; __syncthreads();
    for (int s = 256; s > 0; s >>= 1) {
        if (tid < s) red[tid] = fmaxf(red[tid], red[tid + s]);
        __syncthreads();
    }
    float mx = red[0]; __syncthreads();
    float ex = __expf(e - mx);
    red[tid] = ex; __syncthreads();
    for (int s = 256; s > 0; s >>= 1) {
        if (tid < s) red[tid] += red[tid + s];
        __syncthreads();
    }
    float inv = __fdividef(1.f, red[0]);
    sa[tid] = ex * inv;
    __syncthreads();
    for (int d = tid; d < HID; d += 512) {
        float s0 = 0.f, s1 = 0.f, s2 = 0.f, s3 = 0.f;
        #pragma unroll 4
        for (int t = 0; t < 512; t += 4) {
            s0 += sa[t + 0] * __half2float(g_hs[((size_t)(t + 0) * 64 + b) * 1024 + d]);
            s1 += sa[t + 1] * __half2float(g_hs[((size_t)(t + 1) * 64 + b) * 1024 + d]);
            s2 += sa[t + 2] * __half2float(g_hs[((size_t)(t + 2) * 64 + b) * 1024 + d]);
            s3 += sa[t + 3] * __half2float(g_hs[((size_t)(t + 3) * 64 + b) * 1024 + d]);
        }
        g_ctx[b * HID + d] = (s0 + s1) + (s2 + s3);
    }
}

// ---------------- K7: final classifier (fp32) ----------------
__global__ void final_kernel(const float* __restrict__ WV, const float* __restrict__ bV,
                             float* __restrict__ out) {
    int i = blockIdx.x * blockDim.x + threadIdx.x;
    if (i >= B_ * NCLS) return;
    int b = i / NCLS, n = i % NCLS;
    const float* c = &g_ctx[b * HID];
    const float* w = &WV[n * HID];
    float s = bV[n];
    #pragma unroll 8
    for (int k = 0; k < HID; k++) s += c[k] * w[k];
    out[i] = s;
}

// ---------------- launch ----------------
extern "C" void kernel_launch(void* const* d_in, const int* in_sizes, int n_in,
                              void* d_out, int out_size) {
    const int*   x   = (const int*)  d_in[0];
    const float* emb = (const float*)d_in[1];
    const float* Wg  = (const float*)d_in[2];
    const float* bg  = (const float*)d_in[3];
    const float* Wa  = (const float*)d_in[4];
    const float* va  = (const float*)d_in[5];
    const float* WV  = (const float*)d_in[6];
    const float* bV  = (const float*)d_in[7];
    float* out = (float*)d_out;
    (void)n_in; (void)in_sizes; (void)out_size;

    reset_kernel<<<128, 256>>>();
    convert_kernel<<<2048, 256>>>(Wg, Wa);
    gather_kernel<<<BS_, 256>>>(x, emb);

    gemm_kernel<0, 512><<<dim3(G4 / 128, BS_ / 128), 256>>>(bg);

    const int smem_scan = (64 * 1032 + 32 * 1032) * (int)sizeof(__half);   // 198144
    cudaFuncSetAttribute(scan_kernel, cudaFuncAttributeMaxDynamicSharedMemorySize, smem_scan);
    scan_kernel<<<NCTA, 256, smem_scan>>>();

    gemm_kernel<1, 1024><<<dim3(HID / 128, BS_ / 128), 256>>>(va);

    attn_kernel<<<B_, 512>>>(x);
    final_kernel<<<3, 256>>>(WV, bV, out);
}